// round 8
// baseline (speedup 1.0000x reference)
#include <cuda_runtime.h>
#include <cuda_bf16.h>
#include <cstdint>

#define N 8192
#define D 128
#define TILE_M 128
#define TILE_N 128
#define PSPLIT 4                     // column-range splits per row-block
#define JRANGE (N / PSPLIT)          // 2048 columns per CTA
#define CHUNKS (JRANGE / TILE_N)     // 16
#define NMB (N / TILE_M)             // 64 row-blocks
#define NCTA (NMB * PSPLIT)          // 256
#define NTH 256                      // 8 warps
#define KMAX 16
#define KSLOT 8                      // per-(row,lane) top-k kept
#define NSLOT 16                     // PSPLIT * 4 lane-groups per row

#define ROWSTRIDE 144                // bytes per smem tile row (128 fp8 + 16 pad)
#define ABYTES (TILE_M * ROWSTRIDE)  // 18432 (A region, reused as B1 after hoist)
#define SMEM_AB1 0
#define SMEM_B0  ABYTES
#define SMEM_TOTAL (2 * ABYTES)      // 36864

__device__ __align__(16) uint8_t g_x8[N * D];   // e4m3-quantized normalized rows
__device__ float g_sexp[N * NSLOT];
__device__ float g_cand[N * NSLOT * KSLOT];
__device__ float g_rowpart[N / 8];

__device__ __forceinline__ uint32_t smem_u32(const void* p) {
    uint32_t a;
    asm("{ .reg .u64 t; cvta.to.shared.u64 t, %1; cvt.u32.u64 %0, t; }" : "=r"(a) : "l"(p));
    return a;
}
__device__ __forceinline__ void ldsm_x4(uint32_t& r0, uint32_t& r1, uint32_t& r2,
                                        uint32_t& r3, uint32_t addr) {
    asm volatile("ldmatrix.sync.aligned.m8n8.x4.shared.b16 {%0,%1,%2,%3}, [%4];"
                 : "=r"(r0), "=r"(r1), "=r"(r2), "=r"(r3) : "r"(addr));
}
// FP8 e4m3 MMA, m16n8k32, f32 accumulate
__device__ __forceinline__ void mma_e4m3(float* c, uint32_t a0, uint32_t a1,
                                         uint32_t a2, uint32_t a3,
                                         uint32_t b0, uint32_t b1) {
    asm volatile(
        "mma.sync.aligned.m16n8k32.row.col.f32.e4m3.e4m3.f32 "
        "{%0,%1,%2,%3}, {%4,%5,%6,%7}, {%8,%9}, {%0,%1,%2,%3};"
        : "+f"(c[0]), "+f"(c[1]), "+f"(c[2]), "+f"(c[3])
        : "r"(a0), "r"(a1), "r"(a2), "r"(a3), "r"(b0), "r"(b1));
}
__device__ __forceinline__ void cp16(uint32_t dst, const void* src) {
    asm volatile("cp.async.cg.shared.global [%0], [%1], 16;"
                 :: "r"(dst), "l"(src) : "memory");
}
#define CP_COMMIT() asm volatile("cp.async.commit_group;" ::: "memory")
#define CP_WAIT(nn) asm volatile("cp.async.wait_group %0;" :: "n"(nn) : "memory")

// branchless sorted-insert into descending top-KSLOT list
__device__ __forceinline__ void sorted_insert(float* topv, float x) {
#pragma unroll
    for (int q = 0; q < KSLOT; q++) {
        float t = topv[q];
        bool gt = x > t;
        topv[q] = gt ? x : t;
        x = gt ? t : x;
    }
}

// ---------------------------------------------------------------------------
// Kernel 1: L2-normalize rows -> e4m3. One warp per row.
// ---------------------------------------------------------------------------
__global__ void knn_normalize(const float* __restrict__ x) {
    int row  = blockIdx.x * (blockDim.x >> 5) + (threadIdx.x >> 5);
    int lane = threadIdx.x & 31;
    float4 v = ((const float4*)(x + row * D))[lane];
    float ss = v.x * v.x + v.y * v.y + v.z * v.z + v.w * v.w;
#pragma unroll
    for (int o = 16; o; o >>= 1) ss += __shfl_xor_sync(0xffffffffu, ss, o);
    float inv = rsqrtf(ss);
    float f0 = v.x * inv, f1 = v.y * inv, f2 = v.z * inv, f3 = v.w * inv;
    uint16_t lo, hi;
    asm("cvt.rn.satfinite.e4m3x2.f32 %0, %1, %2;" : "=h"(lo) : "f"(f1), "f"(f0));
    asm("cvt.rn.satfinite.e4m3x2.f32 %0, %1, %2;" : "=h"(hi) : "f"(f3), "f"(f2));
    uint32_t packed = (uint32_t)lo | ((uint32_t)hi << 16);
    ((uint32_t*)(g_x8 + row * D))[lane] = packed;
}

// ---------------------------------------------------------------------------
// Kernel 2: fp8 mma.sync fused GEMM + streaming LSE/top-k.
// Diagonal included everywhere (always the row max); merge drops one max.
// ---------------------------------------------------------------------------
__global__ void __launch_bounds__(NTH, 2) knn_main() {
    extern __shared__ char smem[];
    uint32_t sbase = smem_u32(smem);

    const int tid  = threadIdx.x;
    const int wid  = tid >> 5;
    const int lane = tid & 31;
    const int l4   = lane & 3;

    const int mb = blockIdx.x >> 2;       // row-block 0..63
    const int p  = blockIdx.x & 3;        // column split 0..3
    const int jBase = p * JRANGE;

    const int warpRow = wid * 16;
    const int r0 = warpRow + (lane >> 2);
    const int iGlob0 = mb * TILE_M + r0;
    const int iGlob1 = iGlob0 + 8;

    // A tile -> AB1 region (plain LDG+STS, once). 8 x 16B segs per row.
    for (int it = tid; it < TILE_M * 8; it += NTH) {
        int row = it >> 3, seg = it & 7;
        uint4 v = ((const uint4*)(g_x8 + (mb * TILE_M + row) * D))[seg];
        *(uint4*)(smem + SMEM_AB1 + row * ROWSTRIDE + seg * 16) = v;
    }

    // prefetch B chunk 0 into B0
    {
#pragma unroll
        for (int s = 0; s < 4; s++) {
            int it = tid + s * NTH;
            int row = it >> 3, seg = it & 7;
            cp16(sbase + SMEM_B0 + (uint32_t)(row * ROWSTRIDE + seg * 16),
                 g_x8 + (jBase + row) * D + seg * 16);
        }
        CP_COMMIT();
    }

    // A x4: rows warpRow + (lane&15), k-half (lane>>4)*16 bytes
    uint32_t aAddrBase = sbase + SMEM_AB1
        + (uint32_t)(warpRow + (lane & 15)) * ROWSTRIDE
        + (uint32_t)(lane >> 4) * 16;
    // B x4: n-rows (lane>>4)*8 + (lane&7), k-half ((lane>>3)&1)*16 bytes
    uint32_t bLaneOff =
          (uint32_t)((lane >> 4) * 8 + (lane & 7)) * ROWSTRIDE
        + (uint32_t)((lane >> 3) & 1) * 16;

    CP_WAIT(0);
    __syncthreads();   // A stores + B0 visible to all

    // Hoist A fragments for the whole kernel: 4 k-steps (k32 each) x 4 regs
    uint32_t aF[4][4];
#pragma unroll
    for (int ks = 0; ks < 4; ks++)
        ldsm_x4(aF[ks][0], aF[ks][1], aF[ks][2], aF[ks][3], aAddrBase + ks * 32);

    __syncthreads();   // AB1 region now dead as A -> safe to reuse as B1

    float topv0[KSLOT], topv1[KSLOT];
    float sexp0 = 0.f, sexp1 = 0.f;
#pragma unroll
    for (int t = 0; t < KSLOT; t++) { topv0[t] = -1e30f; topv1[t] = -1e30f; }

    for (int ch = 0; ch < CHUNKS; ch++) {
        const int cur = ch & 1;                       // 0 -> B0, 1 -> AB1
        const uint32_t curOff = cur ? SMEM_AB1 : SMEM_B0;

        if (ch + 1 < CHUNKS) {
            int jn = jBase + (ch + 1) * TILE_N;
            uint32_t dstB = sbase + (cur ? SMEM_B0 : SMEM_AB1);
#pragma unroll
            for (int s = 0; s < 4; s++) {
                int it = tid + s * NTH;
                int row = it >> 3, seg = it & 7;
                cp16(dstB + (uint32_t)(row * ROWSTRIDE + seg * 16),
                     g_x8 + (jn + row) * D + seg * 16);
            }
            CP_COMMIT();
            CP_WAIT(1);   // current chunk's group complete
        } else {
            CP_WAIT(0);
        }
        __syncthreads();

        uint32_t bBase = sbase + curOff + bLaneOff;

#pragma unroll
        for (int tp = 0; tp < 8; tp++) {
            float acc[2][4] = {{0.f, 0.f, 0.f, 0.f}, {0.f, 0.f, 0.f, 0.f}};
#pragma unroll
            for (int ks = 0; ks < 4; ks++) {
                uint32_t b0, b1, b2, b3;
                ldsm_x4(b0, b1, b2, b3,
                        bBase + (uint32_t)tp * (16 * ROWSTRIDE) + ks * 32);
                mma_e4m3(acc[0], aF[ks][0], aF[ks][1], aF[ks][2], aF[ks][3], b0, b1);
                mma_e4m3(acc[1], aF[ks][0], aF[ks][1], aF[ks][2], aF[ks][3], b2, b3);
            }

            // epilogue: no diag check; diag handled in merge (drop one max)
#pragma unroll
            for (int tt = 0; tt < 2; tt++) {
                float v0 = acc[tt][0], v1 = acc[tt][1];
                float v2 = acc[tt][2], v3 = acc[tt][3];
                sexp0 += __expf(v0) + __expf(v1);
                sexp1 += __expf(v2) + __expf(v3);
                if (v0 > topv0[KSLOT - 1]) sorted_insert(topv0, v0);
                if (v1 > topv0[KSLOT - 1]) sorted_insert(topv0, v1);
                if (v2 > topv1[KSLOT - 1]) sorted_insert(topv1, v2);
                if (v3 > topv1[KSLOT - 1]) sorted_insert(topv1, v3);
            }
        }
        __syncthreads();   // all warps done reading buf[cur] before overwrite
    }

    int slot = p * 4 + l4;
    g_sexp[iGlob0 * NSLOT + slot] = sexp0;
    g_sexp[iGlob1 * NSLOT + slot] = sexp1;
#pragma unroll
    for (int t = 0; t < KSLOT; t++) {
        g_cand[(iGlob0 * NSLOT + slot) * KSLOT + t] = topv0[t];
        g_cand[(iGlob1 * NSLOT + slot) * KSLOT + t] = topv1[t];
    }
}

// ---------------------------------------------------------------------------
// Kernel 3: per-row merge (8 rows/block, 1 warp/row) -> block partial.
// 128 candidates include the diagonal (row max) -> k+1 rounds, drop round 0.
// ---------------------------------------------------------------------------
__global__ void __launch_bounds__(256) knn_merge(const int* kptr) {
    __shared__ float wres[8];
    int k = kptr ? *kptr : KMAX;
    if (k > KMAX) k = KMAX;
    if (k < 1) k = 1;

    int wid = threadIdx.x >> 5, lane = threadIdx.x & 31;
    int row = blockIdx.x * 8 + wid;

    float s = (lane < NSLOT) ? g_sexp[row * NSLOT + lane] : 0.f;
#pragma unroll
    for (int o = 16; o; o >>= 1) s += __shfl_xor_sync(0xffffffffu, s, o);
    float lse = logf(s);

    float loc[4];
#pragma unroll
    for (int i = 0; i < 4; i++)
        loc[i] = g_cand[row * (NSLOT * KSLOT) + lane * 4 + i];

    float topsum = 0.f;
    for (int it = 0; it <= k; it++) {      // k+1 rounds; round 0 removes diagonal
        float lm = loc[0]; int li = 0;
#pragma unroll
        for (int i = 1; i < 4; i++)
            if (loc[i] > lm) { lm = loc[i]; li = i; }
        float bv = lm; int bl = lane;
#pragma unroll
        for (int o = 16; o; o >>= 1) {
            float ov = __shfl_xor_sync(0xffffffffu, bv, o);
            int   ol = __shfl_xor_sync(0xffffffffu, bl, o);
            if (ov > bv || (ov == bv && ol < bl)) { bv = ov; bl = ol; }
        }
        if (it > 0) topsum += bv;          // skip diagonal (global row max)
        if (lane == bl) {
#pragma unroll
            for (int i = 0; i < 4; i++)
                if (i == li) loc[i] = -1e30f;
        }
    }
    if (lane == 0) wres[wid] = (float)k * lse - topsum;
    __syncthreads();
    if (threadIdx.x == 0) {
        float a = 0.f;
#pragma unroll
        for (int w = 0; w < 8; w++) a += wres[w];
        g_rowpart[blockIdx.x] = a;
    }
}

// ---------------------------------------------------------------------------
// Kernel 4: deterministic tree reduce of 1024 partials.
// ---------------------------------------------------------------------------
__global__ void knn_finalize(float* __restrict__ out) {
    __shared__ float red[1024];
    int t = threadIdx.x;
    red[t] = g_rowpart[t];
    __syncthreads();
    for (int s = 512; s > 0; s >>= 1) {
        if (t < s) red[t] += red[t + s];
        __syncthreads();
    }
    if (t == 0) out[0] = red[0];
}

// ---------------------------------------------------------------------------
extern "C" void kernel_launch(void* const* d_in, const int* in_sizes, int n_in,
                              void* d_out, int out_size) {
    (void)in_sizes; (void)out_size;
    const float* x    = (const float*)d_in[0];
    const int*   kptr = (n_in >= 2) ? (const int*)d_in[1] : nullptr;

    knn_normalize<<<N / 8, 256>>>(x);

    cudaFuncSetAttribute(knn_main, cudaFuncAttributeMaxDynamicSharedMemorySize, SMEM_TOTAL);
    knn_main<<<NCTA, NTH, SMEM_TOTAL>>>();

    knn_merge<<<N / 8, 256>>>(kptr);
    knn_finalize<<<1, 1024>>>((float*)d_out);
}

// round 9
// speedup vs baseline: 1.2182x; 1.2182x over previous
#include <cuda_runtime.h>
#include <cuda_bf16.h>
#include <cstdint>

#define N 8192
#define D 128
#define TILE_M 128
#define TILE_N 128
#define PSPLIT 4                     // column-range splits per row-block
#define JRANGE (N / PSPLIT)          // 2048 columns per CTA
#define CHUNKS (JRANGE / TILE_N)     // 16
#define NMB (N / TILE_M)             // 64 row-blocks
#define NCTA (NMB * PSPLIT)          // 256
#define NTH 256                      // 8 warps
#define KMAX 16
#define KSLOT 8                      // per-(row,lane) top-k kept
#define NSLOT 16                     // PSPLIT * 4 lane-groups per row

#define ROWSTRIDE 144                // bytes per smem tile row (128 int8 + 16 pad)
#define ABYTES (TILE_M * ROWSTRIDE)  // 18432 (A region, reused as B1 after hoist)
#define SMEM_AB1 0
#define SMEM_B0  ABYTES
#define SMEM_TOTAL (2 * ABYTES)      // 36864

#define QSCALE 127.0f
#define INVQ2  (1.0f / (127.0f * 127.0f))

__device__ __align__(16) uint8_t g_x8[N * D];   // int8-quantized normalized rows
__device__ float g_sexp[N * NSLOT];
__device__ float g_cand[N * NSLOT * KSLOT];
__device__ float g_rowpart[N / 8];

__device__ __forceinline__ uint32_t smem_u32(const void* p) {
    uint32_t a;
    asm("{ .reg .u64 t; cvta.to.shared.u64 t, %1; cvt.u32.u64 %0, t; }" : "=r"(a) : "l"(p));
    return a;
}
__device__ __forceinline__ void ldsm_x4(uint32_t& r0, uint32_t& r1, uint32_t& r2,
                                        uint32_t& r3, uint32_t addr) {
    asm volatile("ldmatrix.sync.aligned.m8n8.x4.shared.b16 {%0,%1,%2,%3}, [%4];"
                 : "=r"(r0), "=r"(r1), "=r"(r2), "=r"(r3) : "r"(addr));
}
// INT8 MMA, m16n8k32, s32 accumulate
__device__ __forceinline__ void mma_s8(int* c, uint32_t a0, uint32_t a1,
                                       uint32_t a2, uint32_t a3,
                                       uint32_t b0, uint32_t b1) {
    asm volatile(
        "mma.sync.aligned.m16n8k32.row.col.s32.s8.s8.s32 "
        "{%0,%1,%2,%3}, {%4,%5,%6,%7}, {%8,%9}, {%0,%1,%2,%3};"
        : "+r"(c[0]), "+r"(c[1]), "+r"(c[2]), "+r"(c[3])
        : "r"(a0), "r"(a1), "r"(a2), "r"(a3), "r"(b0), "r"(b1));
}
__device__ __forceinline__ void cp16(uint32_t dst, const void* src) {
    asm volatile("cp.async.cg.shared.global [%0], [%1], 16;"
                 :: "r"(dst), "l"(src) : "memory");
}
#define CP_COMMIT() asm volatile("cp.async.commit_group;" ::: "memory")
#define CP_WAIT(nn) asm volatile("cp.async.wait_group %0;" :: "n"(nn) : "memory")

// branchless sorted-insert into descending top-KSLOT list
__device__ __forceinline__ void sorted_insert(float* topv, float x) {
#pragma unroll
    for (int q = 0; q < KSLOT; q++) {
        float t = topv[q];
        bool gt = x > t;
        topv[q] = gt ? x : t;
        x = gt ? t : x;
    }
}

// ---------------------------------------------------------------------------
// Kernel 1: L2-normalize rows -> int8 (scale 127). One warp per row.
// ---------------------------------------------------------------------------
__global__ void knn_normalize(const float* __restrict__ x) {
    int row  = blockIdx.x * (blockDim.x >> 5) + (threadIdx.x >> 5);
    int lane = threadIdx.x & 31;
    float4 v = ((const float4*)(x + row * D))[lane];
    float ss = v.x * v.x + v.y * v.y + v.z * v.z + v.w * v.w;
#pragma unroll
    for (int o = 16; o; o >>= 1) ss += __shfl_xor_sync(0xffffffffu, ss, o);
    float inv = rsqrtf(ss) * QSCALE;
    int q0 = __float2int_rn(v.x * inv);
    int q1 = __float2int_rn(v.y * inv);
    int q2 = __float2int_rn(v.z * inv);
    int q3 = __float2int_rn(v.w * inv);
    uint32_t packed = (uint32_t)(q0 & 0xFF) | ((uint32_t)(q1 & 0xFF) << 8)
                    | ((uint32_t)(q2 & 0xFF) << 16) | ((uint32_t)(q3 & 0xFF) << 24);
    ((uint32_t*)(g_x8 + row * D))[lane] = packed;
}

// ---------------------------------------------------------------------------
// Kernel 2: int8 mma.sync fused GEMM + streaming LSE/top-k.
// Diagonal included everywhere (always the row max); merge drops one max.
// ---------------------------------------------------------------------------
__global__ void __launch_bounds__(NTH, 2) knn_main() {
    extern __shared__ char smem[];
    uint32_t sbase = smem_u32(smem);

    const int tid  = threadIdx.x;
    const int wid  = tid >> 5;
    const int lane = tid & 31;
    const int l4   = lane & 3;

    const int mb = blockIdx.x >> 2;       // row-block 0..63
    const int p  = blockIdx.x & 3;        // column split 0..3
    const int jBase = p * JRANGE;

    const int warpRow = wid * 16;
    const int r0 = warpRow + (lane >> 2);
    const int iGlob0 = mb * TILE_M + r0;
    const int iGlob1 = iGlob0 + 8;

    // A tile -> AB1 region (plain LDG+STS, once). 8 x 16B segs per row.
    for (int it = tid; it < TILE_M * 8; it += NTH) {
        int row = it >> 3, seg = it & 7;
        uint4 v = ((const uint4*)(g_x8 + (mb * TILE_M + row) * D))[seg];
        *(uint4*)(smem + SMEM_AB1 + row * ROWSTRIDE + seg * 16) = v;
    }

    // prefetch B chunk 0 into B0
    {
#pragma unroll
        for (int s = 0; s < 4; s++) {
            int it = tid + s * NTH;
            int row = it >> 3, seg = it & 7;
            cp16(sbase + SMEM_B0 + (uint32_t)(row * ROWSTRIDE + seg * 16),
                 g_x8 + (jBase + row) * D + seg * 16);
        }
        CP_COMMIT();
    }

    uint32_t aAddrBase = sbase + SMEM_AB1
        + (uint32_t)(warpRow + (lane & 15)) * ROWSTRIDE
        + (uint32_t)(lane >> 4) * 16;
    uint32_t bLaneOff =
          (uint32_t)((lane >> 4) * 8 + (lane & 7)) * ROWSTRIDE
        + (uint32_t)((lane >> 3) & 1) * 16;

    CP_WAIT(0);
    __syncthreads();   // A stores + B0 visible to all

    // Hoist A fragments for the whole kernel: 4 k-steps (k32 each) x 4 regs
    uint32_t aF[4][4];
#pragma unroll
    for (int ks = 0; ks < 4; ks++)
        ldsm_x4(aF[ks][0], aF[ks][1], aF[ks][2], aF[ks][3], aAddrBase + ks * 32);

    __syncthreads();   // AB1 region now dead as A -> safe to reuse as B1

    float topv0[KSLOT], topv1[KSLOT];
    float sexp0 = 0.f, sexp1 = 0.f;
#pragma unroll
    for (int t = 0; t < KSLOT; t++) { topv0[t] = -1e30f; topv1[t] = -1e30f; }

    for (int ch = 0; ch < CHUNKS; ch++) {
        const int cur = ch & 1;                       // 0 -> B0, 1 -> AB1
        const uint32_t curOff = cur ? SMEM_AB1 : SMEM_B0;

        if (ch + 1 < CHUNKS) {
            int jn = jBase + (ch + 1) * TILE_N;
            uint32_t dstB = sbase + (cur ? SMEM_B0 : SMEM_AB1);
#pragma unroll
            for (int s = 0; s < 4; s++) {
                int it = tid + s * NTH;
                int row = it >> 3, seg = it & 7;
                cp16(dstB + (uint32_t)(row * ROWSTRIDE + seg * 16),
                     g_x8 + (jn + row) * D + seg * 16);
            }
            CP_COMMIT();
            CP_WAIT(1);   // current chunk's group complete
        } else {
            CP_WAIT(0);
        }
        __syncthreads();

        uint32_t bBase = sbase + curOff + bLaneOff;

#pragma unroll
        for (int tp = 0; tp < 8; tp++) {
            int acc[2][4] = {{0, 0, 0, 0}, {0, 0, 0, 0}};
#pragma unroll
            for (int ks = 0; ks < 4; ks++) {
                uint32_t b0, b1, b2, b3;
                ldsm_x4(b0, b1, b2, b3,
                        bBase + (uint32_t)tp * (16 * ROWSTRIDE) + ks * 32);
                mma_s8(acc[0], aF[ks][0], aF[ks][1], aF[ks][2], aF[ks][3], b0, b1);
                mma_s8(acc[1], aF[ks][0], aF[ks][1], aF[ks][2], aF[ks][3], b2, b3);
            }

            // epilogue: scale to cosine, no diag check (merge drops one max)
#pragma unroll
            for (int tt = 0; tt < 2; tt++) {
                float v0 = __int2float_rn(acc[tt][0]) * INVQ2;
                float v1 = __int2float_rn(acc[tt][1]) * INVQ2;
                float v2 = __int2float_rn(acc[tt][2]) * INVQ2;
                float v3 = __int2float_rn(acc[tt][3]) * INVQ2;
                sexp0 += __expf(v0) + __expf(v1);
                sexp1 += __expf(v2) + __expf(v3);
                if (v0 > topv0[KSLOT - 1]) sorted_insert(topv0, v0);
                if (v1 > topv0[KSLOT - 1]) sorted_insert(topv0, v1);
                if (v2 > topv1[KSLOT - 1]) sorted_insert(topv1, v2);
                if (v3 > topv1[KSLOT - 1]) sorted_insert(topv1, v3);
            }
        }
        __syncthreads();   // all warps done reading buf[cur] before overwrite
    }

    int slot = p * 4 + l4;
    g_sexp[iGlob0 * NSLOT + slot] = sexp0;
    g_sexp[iGlob1 * NSLOT + slot] = sexp1;
#pragma unroll
    for (int t = 0; t < KSLOT; t++) {
        g_cand[(iGlob0 * NSLOT + slot) * KSLOT + t] = topv0[t];
        g_cand[(iGlob1 * NSLOT + slot) * KSLOT + t] = topv1[t];
    }
}

// ---------------------------------------------------------------------------
// Kernel 3: per-row merge (8 rows/block, 1 warp/row) -> block partial.
// 128 candidates include the diagonal (row max) -> k+1 rounds, drop round 0.
// ---------------------------------------------------------------------------
__global__ void __launch_bounds__(256) knn_merge(const int* kptr) {
    __shared__ float wres[8];
    int k = kptr ? *kptr : KMAX;
    if (k > KMAX) k = KMAX;
    if (k < 1) k = 1;

    int wid = threadIdx.x >> 5, lane = threadIdx.x & 31;
    int row = blockIdx.x * 8 + wid;

    float s = (lane < NSLOT) ? g_sexp[row * NSLOT + lane] : 0.f;
#pragma unroll
    for (int o = 16; o; o >>= 1) s += __shfl_xor_sync(0xffffffffu, s, o);
    float lse = logf(s);

    float loc[4];
#pragma unroll
    for (int i = 0; i < 4; i++)
        loc[i] = g_cand[row * (NSLOT * KSLOT) + lane * 4 + i];

    float topsum = 0.f;
    for (int it = 0; it <= k; it++) {      // k+1 rounds; round 0 removes diagonal
        float lm = loc[0]; int li = 0;
#pragma unroll
        for (int i = 1; i < 4; i++)
            if (loc[i] > lm) { lm = loc[i]; li = i; }
        float bv = lm; int bl = lane;
#pragma unroll
        for (int o = 16; o; o >>= 1) {
            float ov = __shfl_xor_sync(0xffffffffu, bv, o);
            int   ol = __shfl_xor_sync(0xffffffffu, bl, o);
            if (ov > bv || (ov == bv && ol < bl)) { bv = ov; bl = ol; }
        }
        if (it > 0) topsum += bv;          // skip diagonal (global row max)
        if (lane == bl) {
#pragma unroll
            for (int i = 0; i < 4; i++)
                if (i == li) loc[i] = -1e30f;
        }
    }
    if (lane == 0) wres[wid] = (float)k * lse - topsum;
    __syncthreads();
    if (threadIdx.x == 0) {
        float a = 0.f;
#pragma unroll
        for (int w = 0; w < 8; w++) a += wres[w];
        g_rowpart[blockIdx.x] = a;
    }
}

// ---------------------------------------------------------------------------
// Kernel 4: deterministic tree reduce of 1024 partials.
// ---------------------------------------------------------------------------
__global__ void knn_finalize(float* __restrict__ out) {
    __shared__ float red[1024];
    int t = threadIdx.x;
    red[t] = g_rowpart[t];
    __syncthreads();
    for (int s = 512; s > 0; s >>= 1) {
        if (t < s) red[t] += red[t + s];
        __syncthreads();
    }
    if (t == 0) out[0] = red[0];
}

// ---------------------------------------------------------------------------
extern "C" void kernel_launch(void* const* d_in, const int* in_sizes, int n_in,
                              void* d_out, int out_size) {
    (void)in_sizes; (void)out_size;
    const float* x    = (const float*)d_in[0];
    const int*   kptr = (n_in >= 2) ? (const int*)d_in[1] : nullptr;

    knn_normalize<<<N / 8, 256>>>(x);

    cudaFuncSetAttribute(knn_main, cudaFuncAttributeMaxDynamicSharedMemorySize, SMEM_TOTAL);
    knn_main<<<NCTA, NTH, SMEM_TOTAL>>>();

    knn_merge<<<N / 8, 256>>>(kptr);
    knn_finalize<<<1, 1024>>>((float*)d_out);
}